// round 3
// baseline (speedup 1.0000x reference)
#include <cuda_runtime.h>
#include <math.h>

// Problem constants (shapes fixed by the dataset)
#define NMAX 50000
#define EMAX 800000
#define F    256   // nfeat == nhid*nheads == hid
#define NH   8     // heads
#define FH   32    // per-head dim
#define NC   40    // nclass
#define NS   128   // nstruc

// ---------------- scratch (device globals: allocation-free) ----------------
__device__ float g_Wcat[F * F];                   // repacked W_att
__device__ float g_H[(size_t)NMAX * F];           // per-head features (concat)
__device__ float g_s1[NMAX * NH];
__device__ float g_s2[NMAX * NH];
__device__ float g_rowsum[NMAX * NH];
__device__ float g_hp[(size_t)NMAX * F];          // hp, then h1 in place
__device__ float g_support[(size_t)NMAX * F];
__device__ float g_h2[(size_t)NMAX * F];
__device__ float g_ho[NMAX * NC];
__device__ float g_s1o[NMAX];
__device__ float g_s2o[NMAX];
__device__ float g_rowsumo[NMAX];
__device__ float g_hpo[NMAX * NC];

// vector reduction helper (sm_90+): global float4 add without return
__device__ __forceinline__ void red_add_v4(float* dst, float4 v) {
    asm volatile("red.global.add.v4.f32 [%0], {%1, %2, %3, %4};"
                 :: "l"(dst), "f"(v.x), "f"(v.y), "f"(v.z), "f"(v.w)
                 : "memory");
}

// ---------------- W_att [8,256,32] -> W_cat [256, 256] ----------------
// Wcat[f, i*32+j] = W_att[i, f, j]
__global__ void make_wcat(const float* __restrict__ W_att, float* __restrict__ Wcat) {
    int idx = blockIdx.x * blockDim.x + threadIdx.x;   // 65536 elems
    if (idx >= F * F) return;
    int f = idx >> 8;
    int c = idx & 255;
    int i = c >> 5, j = c & 31;
    Wcat[idx] = W_att[((size_t)i * F + f) * FH + j];
}

// ---------------- zero/bias init of accumulators ----------------
__global__ void init_buffers(float* __restrict__ hp, float* __restrict__ rowsum,
                             float* __restrict__ h2, const float* __restrict__ b_gc,
                             float* __restrict__ rowsumo, float* __restrict__ hpo, int N) {
    int idx = blockIdx.x * blockDim.x + threadIdx.x;
    int total = N * F;
    if (idx >= total) return;
    hp[idx] = 0.f;
    h2[idx] = b_gc[idx & 255];
    if (idx < N * NH) rowsum[idx] = 0.f;
    if (idx < N)      rowsumo[idx] = 0.f;
    if (idx < N * NC) hpo[idx] = 0.f;
}

// ---------------- tiled SGEMM: C[M,Nc] = A[M,K=256] @ B[256,Nc] (+bias) ----------------
// BM=BN=128, BK=8, 256 threads, 8x8 microtile, float4 global loads,
// double-buffered shared memory (1 syncthreads per k-step).
// Requires Nc % 4 == 0 (40, 128, 256 all satisfy; row strides are 16B-aligned).
__global__ void sgemm128(const float* __restrict__ A, const float* __restrict__ B,
                         const float* __restrict__ bias, float* __restrict__ C,
                         int M, int Nc) {
    const int K = 256;
    __shared__ float As[2][8][128];   // transposed A tile: As[buf][k][m]
    __shared__ float Bs[2][8][128];   // Bs[buf][k][n]
    int tid = threadIdx.x;
    int tx = tid & 15;             // 0..15 -> 8 cols each
    int ty = tid >> 4;             // 0..15 -> 8 rows each
    int row0 = blockIdx.y * 128;
    int col0 = blockIdx.x * 128;

    // A tile load mapping: 128 rows x 8 k = 1024 floats = 256 x float4
    int ar = tid >> 1;             // 0..127
    int ak = (tid & 1) * 4;        // 0 or 4
    // B tile load mapping: 8 k-rows x 128 cols = 256 x float4
    int bk = tid >> 5;             // 0..7
    int bc = (tid & 31) * 4;       // 0..124

    bool a_ok = (row0 + ar < M);
    bool b_ok = (col0 + bc < Nc);
    const float* Aptr = A + (size_t)(row0 + ar) * K + ak;
    const float* Bptr = B + (size_t)bk * Nc + col0 + bc;

    float acc[8][8] = {};

    // prologue: stage k0 = 0 into buffer 0
    {
        float4 av = a_ok ? *(const float4*)(Aptr) : make_float4(0.f, 0.f, 0.f, 0.f);
        As[0][ak + 0][ar] = av.x;
        As[0][ak + 1][ar] = av.y;
        As[0][ak + 2][ar] = av.z;
        As[0][ak + 3][ar] = av.w;
        float4 bv = b_ok ? *(const float4*)(Bptr) : make_float4(0.f, 0.f, 0.f, 0.f);
        *(float4*)&Bs[0][bk][bc] = bv;
    }
    __syncthreads();

    int cur = 0;
    for (int k0 = 0; k0 < K; k0 += 8) {
        float4 av, bv;
        bool have_next = (k0 + 8 < K);
        if (have_next) {
            av = a_ok ? *(const float4*)(Aptr + k0 + 8) : make_float4(0.f, 0.f, 0.f, 0.f);
            bv = b_ok ? *(const float4*)(Bptr + (size_t)(k0 + 8) * Nc) : make_float4(0.f, 0.f, 0.f, 0.f);
        }

        #pragma unroll
        for (int kk = 0; kk < 8; kk++) {
            float ra[8], rb[8];
            *(float4*)(ra)     = *(const float4*)&As[cur][kk][ty * 8];
            *(float4*)(ra + 4) = *(const float4*)&As[cur][kk][ty * 8 + 4];
            *(float4*)(rb)     = *(const float4*)&Bs[cur][kk][tx * 8];
            *(float4*)(rb + 4) = *(const float4*)&Bs[cur][kk][tx * 8 + 4];
            #pragma unroll
            for (int i = 0; i < 8; i++)
                #pragma unroll
                for (int j = 0; j < 8; j++)
                    acc[i][j] += ra[i] * rb[j];
        }

        if (have_next) {
            int nxt = cur ^ 1;
            As[nxt][ak + 0][ar] = av.x;
            As[nxt][ak + 1][ar] = av.y;
            As[nxt][ak + 2][ar] = av.z;
            As[nxt][ak + 3][ar] = av.w;
            *(float4*)&Bs[nxt][bk][bc] = bv;
            __syncthreads();
            cur = nxt;
        }
    }

    #pragma unroll
    for (int i = 0; i < 8; i++) {
        int r = row0 + ty * 8 + i;
        if (r >= M) continue;
        #pragma unroll
        for (int j = 0; j < 8; j++) {
            int c = col0 + tx * 8 + j;
            if (c < Nc) {
                float v = acc[i][j];
                if (bias) v += bias[c];
                C[(size_t)r * Nc + c] = v;
            }
        }
    }
}

// ---------------- per-node attention scores s1,s2 [N,8] ----------------
// one block = one node; warp w = head w; lane j covers feature j
__global__ void attn_scores(const float* __restrict__ H, const float* __restrict__ a1,
                            const float* __restrict__ a2, float* __restrict__ s1,
                            float* __restrict__ s2, int N) {
    int n = blockIdx.x;
    if (n >= N) return;
    int w = threadIdx.x >> 5;
    int lane = threadIdx.x & 31;
    float h = H[(size_t)n * F + w * FH + lane];
    float v1 = h * a1[w * FH + lane];
    float v2 = h * a2[w * FH + lane];
    #pragma unroll
    for (int o = 16; o > 0; o >>= 1) {
        v1 += __shfl_xor_sync(0xffffffffu, v1, o);
        v2 += __shfl_xor_sync(0xffffffffu, v2, o);
    }
    if (lane == 0) { s1[n * NH + w] = v1; s2[n * NH + w] = v2; }
}

// ---------------- fused edge pass: att coeff + rowsum + hp scatter ----------------
// 4 edges / CTA(256); 64 threads per edge; thread u handles floats 4u..4u+3
// (head = u>>3). No materialized att buffer.
__global__ void edge_fused(const int* __restrict__ row, const int* __restrict__ col,
                           const float* __restrict__ s1, const float* __restrict__ s2,
                           const float* __restrict__ H, float* __restrict__ hp,
                           float* __restrict__ rowsum, int E) {
    int e = blockIdx.x * 4 + (threadIdx.x >> 6);
    if (e >= E) return;
    int u = threadIdx.x & 63;
    int head = u >> 3;
    int r = __ldg(row + e), c = __ldg(col + e);
    float lg = __ldg(s1 + r * NH + head) + __ldg(s2 + c * NH + head);
    float l = lg > 0.f ? lg : 0.2f * lg;
    float a = __expf(-l);
    if ((u & 7) == 0) atomicAdd(&rowsum[r * NH + head], a);
    float4 h4 = *(const float4*)(H + (size_t)c * F + 4 * u);
    red_add_v4(hp + (size_t)r * F + 4 * u,
               make_float4(a * h4.x, a * h4.y, a * h4.z, a * h4.w));
}

// ---------------- normalize + elu -> h1 (in place over hp) ----------------
__global__ void norm_elu(float* __restrict__ hp, const float* __restrict__ rowsum, int N) {
    int idx = blockIdx.x * blockDim.x + threadIdx.x;
    if (idx >= N * F) return;
    int n = idx >> 8;
    int i = (idx & 255) >> 5;
    float v = hp[idx] / (rowsum[n * NH + i] + 1e-16f);
    hp[idx] = v > 0.f ? v : (expf(v) - 1.f);
}

// ---------------- GraphConv scatter: h2[row] += support[col] ----------------
__global__ void gc_aggregate(const int* __restrict__ row, const int* __restrict__ col,
                             const float* __restrict__ sup, float* __restrict__ h2, int E) {
    int e = blockIdx.x * 4 + (threadIdx.x >> 6);
    if (e >= E) return;
    int u = threadIdx.x & 63;
    int r = __ldg(row + e), c = __ldg(col + e);
    float4 s4 = *(const float4*)(sup + (size_t)c * F + 4 * u);
    red_add_v4(h2 + (size_t)r * F + 4 * u, s4);
}

// ---------------- output-head scores (dim 40): one warp per node ----------------
__global__ void out_scores(const float* __restrict__ ho, const float* __restrict__ a1o,
                           const float* __restrict__ a2o, float* __restrict__ s1o,
                           float* __restrict__ s2o, int N) {
    int n = blockIdx.x * 8 + (threadIdx.x >> 5);
    if (n >= N) return;
    int lane = threadIdx.x & 31;
    float h0 = ho[(size_t)n * NC + lane];
    float v1 = h0 * a1o[lane];
    float v2 = h0 * a2o[lane];
    if (lane < NC - 32) {
        float h1v = ho[(size_t)n * NC + 32 + lane];
        v1 += h1v * a1o[32 + lane];
        v2 += h1v * a2o[32 + lane];
    }
    #pragma unroll
    for (int o = 16; o > 0; o >>= 1) {
        v1 += __shfl_xor_sync(0xffffffffu, v1, o);
        v2 += __shfl_xor_sync(0xffffffffu, v2, o);
    }
    if (lane == 0) { s1o[n] = v1; s2o[n] = v2; }
}

// ---------------- fused output edge pass ----------------
// 16 threads per edge (q = 0..9 handle float4 chunks of the 40-dim row,
// q = 10..15 idle for feature work). q==0 accumulates rowsumo. Attention
// coefficient recomputed per thread from cached s1o/s2o (cheap, saves the
// atto[E] buffer + a full extra E-pass).
__global__ void out_fused(const int* __restrict__ row, const int* __restrict__ col,
                          const float* __restrict__ s1o, const float* __restrict__ s2o,
                          const float* __restrict__ ho, float* __restrict__ hpo,
                          float* __restrict__ rowsumo, int E) {
    int e = blockIdx.x * 16 + (threadIdx.x >> 4);
    if (e >= E) return;
    int q = threadIdx.x & 15;
    int r = __ldg(row + e), c = __ldg(col + e);
    float lg = __ldg(s1o + r) + __ldg(s2o + c);
    float l = lg > 0.f ? lg : 0.2f * lg;
    float a = __expf(-l);
    if (q == 0) atomicAdd(&rowsumo[r], a);
    if (q < 10) {
        float4 h4 = *(const float4*)(ho + (size_t)c * NC + 4 * q);
        red_add_v4(hpo + (size_t)r * NC + 4 * q,
                   make_float4(a * h4.x, a * h4.y, a * h4.z, a * h4.w));
    }
}

// ---------------- normalize + elu + log_softmax over 40 classes ----------------
__global__ void final_xo(const float* __restrict__ hpo, const float* __restrict__ rowsumo,
                         float* __restrict__ out, int N) {
    int n = blockIdx.x * 8 + (threadIdx.x >> 5);
    if (n >= N) return;
    int lane = threadIdx.x & 31;
    float rs = rowsumo[n] + 1e-16f;
    float x0 = hpo[(size_t)n * NC + lane] / rs;
    x0 = x0 > 0.f ? x0 : (expf(x0) - 1.f);
    float x1 = -1e30f;
    if (lane < NC - 32) {
        x1 = hpo[(size_t)n * NC + 32 + lane] / rs;
        x1 = x1 > 0.f ? x1 : (expf(x1) - 1.f);
    }
    float m = fmaxf(x0, x1);
    #pragma unroll
    for (int o = 16; o > 0; o >>= 1) m = fmaxf(m, __shfl_xor_sync(0xffffffffu, m, o));
    float s = expf(x0 - m) + (lane < NC - 32 ? expf(x1 - m) : 0.f);
    #pragma unroll
    for (int o = 16; o > 0; o >>= 1) s += __shfl_xor_sync(0xffffffffu, s, o);
    float lse = logf(s) + m;
    out[(size_t)n * NC + lane] = x0 - lse;
    if (lane < NC - 32) out[(size_t)n * NC + 32 + lane] = x1 - lse;
}

// =============================================================================
extern "C" void kernel_launch(void* const* d_in, const int* in_sizes, int n_in,
                              void* d_out, int out_size) {
    const float* x     = (const float*)d_in[0];
    const int*   eidx  = (const int*)d_in[1];
    const float* W_att = (const float*)d_in[2];
    const float* a1    = (const float*)d_in[3];
    const float* a2    = (const float*)d_in[4];
    const float* W_out = (const float*)d_in[5];
    const float* a1o   = (const float*)d_in[6];
    const float* a2o   = (const float*)d_in[7];
    const float* W_gc  = (const float*)d_in[8];
    const float* b_gc  = (const float*)d_in[9];
    const float* W_enc = (const float*)d_in[10];
    const float* b_enc = (const float*)d_in[11];
    float* out = (float*)d_out;

    int N = in_sizes[0] / F;
    int E = in_sizes[1] / 2;
    const int* row = eidx;
    const int* col = eidx + E;

    float *Wcat, *H, *s1, *s2, *rowsum, *hp, *support, *h2;
    float *ho, *s1o, *s2o, *rowsumo, *hpo;
    cudaGetSymbolAddress((void**)&Wcat,    g_Wcat);
    cudaGetSymbolAddress((void**)&H,       g_H);
    cudaGetSymbolAddress((void**)&s1,      g_s1);
    cudaGetSymbolAddress((void**)&s2,      g_s2);
    cudaGetSymbolAddress((void**)&rowsum,  g_rowsum);
    cudaGetSymbolAddress((void**)&hp,      g_hp);
    cudaGetSymbolAddress((void**)&support, g_support);
    cudaGetSymbolAddress((void**)&h2,      g_h2);
    cudaGetSymbolAddress((void**)&ho,      g_ho);
    cudaGetSymbolAddress((void**)&s1o,     g_s1o);
    cudaGetSymbolAddress((void**)&s2o,     g_s2o);
    cudaGetSymbolAddress((void**)&rowsumo, g_rowsumo);
    cudaGetSymbolAddress((void**)&hpo,     g_hpo);

    // 0) repack W_att, init accumulators
    make_wcat<<<(F * F + 255) / 256, 256>>>(W_att, Wcat);
    init_buffers<<<(N * F + 255) / 256, 256>>>(hp, rowsum, h2, b_gc, rowsumo, hpo, N);

    // 1) H = x @ Wcat   [N,256]
    {
        dim3 grid((F + 127) / 128, (N + 127) / 128);
        sgemm128<<<grid, 256>>>(x, Wcat, nullptr, H, N, F);
    }

    // 2) per-node attention scores
    attn_scores<<<N, 256>>>(H, a1, a2, s1, s2, N);

    // 3+4) fused: per-edge att coeff, rowsum accumulation, hp[row] += att*H[col]
    edge_fused<<<(E + 3) / 4, 256>>>(row, col, s1, s2, H, hp, rowsum, E);

    // 5) h1 = elu(hp / rowsum)  (in place)
    norm_elu<<<(N * F + 255) / 256, 256>>>(hp, rowsum, N);

    // 6) support = h1 @ W_gc
    {
        dim3 grid((F + 127) / 128, (N + 127) / 128);
        sgemm128<<<grid, 256>>>(hp, W_gc, nullptr, support, N, F);
    }

    // 7) h2 = b_gc + sum support[col] over edges
    gc_aggregate<<<(E + 3) / 4, 256>>>(row, col, support, h2, E);

    // 8) ho = h2 @ W_out  [N,40]
    {
        dim3 grid((NC + 127) / 128, (N + 127) / 128);
        sgemm128<<<grid, 256>>>(h2, W_out, nullptr, ho, N, NC);
    }

    // 9) output-head attention (scores + fused edge pass)
    out_scores<<<(N + 7) / 8, 256>>>(ho, a1o, a2o, s1o, s2o, N);
    out_fused<<<(E + 15) / 16, 256>>>(row, col, s1o, s2o, ho, hpo, rowsumo, E);

    // 10) xo = log_softmax(elu(hpo / rowsumo)) -> out[0 : N*40]
    final_xo<<<(N + 7) / 8, 256>>>(hpo, rowsumo, out, N);

    // 11) y = h1 @ W_enc + b_enc ; z = h2 @ W_enc + b_enc
    {
        dim3 grid((NS + 127) / 128, (N + 127) / 128);
        sgemm128<<<grid, 256>>>(hp, W_enc, b_enc, out + (size_t)N * NC, N, NS);
        sgemm128<<<grid, 256>>>(h2, W_enc, b_enc, out + (size_t)N * (NC + NS), N, NS);
    }
}

// round 6
// speedup vs baseline: 1.0882x; 1.0882x over previous
#include <cuda_runtime.h>
#include <cuda_bf16.h>
#include <math.h>

// Problem constants (shapes fixed by the dataset)
#define NMAX 50000
#define EMAX 800000
#define F    256   // nfeat == nhid*nheads == hid
#define NH   8     // heads
#define FH   32    // per-head dim
#define NC   40    // nclass
#define NS   128   // nstruc
// bf16x3 split: K2 = 3*256 = 768 -> A = [Ahi|Alo|Ahi], B = [Bhi|Bhi|Blo]
#define KT   48    // k16 tiles in K2
#define MT_MAX 3125  // NMAX/16

// ---------------- scratch (device globals: allocation-free) ----------------
__device__ float g_Wcat[F * F];                   // repacked W_att
__device__ float g_H[(size_t)NMAX * F];           // per-head features (concat)
__device__ float g_s1[NMAX * NH];
__device__ float g_s2[NMAX * NH];
__device__ float g_rowsum[NMAX * NH];
__device__ float g_hp[(size_t)NMAX * F];          // hp, then h1 in place
__device__ float g_support[(size_t)NMAX * F];
__device__ float g_h2[(size_t)NMAX * F];
__device__ float g_ho[NMAX * NC];
__device__ float g_s1o[NMAX];
__device__ float g_s2o[NMAX];
__device__ float g_rowsumo[NMAX];
__device__ float g_hpo[NMAX * NC];

// bf16 split operands in mma-fragment order
// A: [m_tiles][KT][32 lanes] x uint4 (8 bf16)
__device__ uint4 g_A2a[(size_t)MT_MAX * KT * 32];
__device__ uint4 g_A2b[(size_t)MT_MAX * KT * 32];
// B: [n_tiles][KT][32 lanes] x uint2 (4 bf16)
__device__ uint2 g_B2att[32 * KT * 32];
__device__ uint2 g_B2gc [32 * KT * 32];
__device__ uint2 g_B2out[ 5 * KT * 32];
__device__ uint2 g_B2enc[16 * KT * 32];

// vector reduction helper (sm_90+): global float4 add without return
__device__ __forceinline__ void red_add_v4(float* dst, float4 v) {
    asm volatile("red.global.add.v4.f32 [%0], {%1, %2, %3, %4};"
                 :: "l"(dst), "f"(v.x), "f"(v.y), "f"(v.z), "f"(v.w)
                 : "memory");
}

// bf16 mma: D += A(16x16) * B(16x8), row.col, fp32 accum
__device__ __forceinline__ void mma16816(float* d, const uint4& a, const uint2& b) {
    asm volatile(
        "mma.sync.aligned.m16n8k16.row.col.f32.bf16.bf16.f32 "
        "{%0,%1,%2,%3}, {%4,%5,%6,%7}, {%8,%9}, {%0,%1,%2,%3};"
        : "+f"(d[0]), "+f"(d[1]), "+f"(d[2]), "+f"(d[3])
        : "r"(a.x), "r"(a.y), "r"(a.z), "r"(a.w), "r"(b.x), "r"(b.y));
}

__device__ __forceinline__ unsigned short bf_hi(float a) {
    return __bfloat16_as_ushort(__float2bfloat16(a));
}
__device__ __forceinline__ unsigned short bf_lo(float a) {
    float h = __bfloat162float(__float2bfloat16(a));
    return __bfloat16_as_ushort(__float2bfloat16(a - h));
}

// A split mapping over tripled k2: [0,F) hi, [F,2F) lo, [2F,3F) hi
__device__ __forceinline__ unsigned short split_elem_a(const float* base, int k2) {
    if (k2 < F)       return bf_hi(base[k2]);
    else if (k2 < 2*F) return bf_lo(base[k2 - F]);
    else               return bf_hi(base[k2 - 2*F]);
}

// ---------------- A [M,256] fp32 -> fragment-order bf16x3 ----------------
// word idx: r = idx&3, lane = (idx>>2)&31, then kt = rest%KT, mt = rest/KT
__global__ void split_a(const float* __restrict__ A, unsigned* __restrict__ out,
                        int m_tiles, int M) {
    long long idx = (long long)blockIdx.x * blockDim.x + threadIdx.x;
    long long total = (long long)m_tiles * KT * 32 * 4;
    if (idx >= total) return;
    int r    = (int)(idx & 3);
    int lane = (int)((idx >> 2) & 31);
    long long rest = idx >> 7;
    int kt   = (int)(rest % KT);
    int mt   = (int)(rest / KT);
    int g = lane >> 2, t2 = (lane & 3) * 2;
    int row   = mt * 16 + g + (r & 1) * 8;
    int kbase = kt * 16 + t2 + (r >> 1) * 8;
    unsigned w = 0;
    if (row < M) {
        const float* base = A + (size_t)row * F;
        unsigned short e0 = split_elem_a(base, kbase);
        unsigned short e1 = split_elem_a(base, kbase + 1);
        w = (unsigned)e0 | ((unsigned)e1 << 16);
    }
    out[idx] = w;
}

// ---------------- B [256,Nc] fp32 -> fragment-order bf16x3 ----------------
// B mapping over tripled k2: [0,F) hi, [F,2F) hi, [2F,3F) lo
__global__ void split_b(const float* __restrict__ B, unsigned* __restrict__ out,
                        int n_tiles, int Nc) {
    int idx = blockIdx.x * blockDim.x + threadIdx.x;
    int total = n_tiles * KT * 32 * 2;
    if (idx >= total) return;
    int r    = idx & 1;
    int lane = (idx >> 1) & 31;
    int rest = idx >> 6;
    int kt   = rest % KT;
    int nt   = rest / KT;
    int g = lane >> 2, t2 = (lane & 3) * 2;
    int n = nt * 8 + g;
    int kbase = kt * 16 + t2 + r * 8;
    unsigned w = 0;
    #pragma unroll
    for (int p = 0; p < 2; p++) {
        int k2 = kbase + p;
        unsigned short bits;
        if (k2 < 2*F) {
            int k = (k2 < F) ? k2 : (k2 - F);
            bits = bf_hi(B[(size_t)k * Nc + n]);
        } else {
            bits = bf_lo(B[(size_t)(k2 - 2*F) * Nc + n]);
        }
        w |= (unsigned)bits << (16 * p);
    }
    out[idx] = w;
}

// ---------------- fragment loads ----------------
__device__ __forceinline__ void ldA(const uint4* __restrict__ Af, int mt0, int m_tiles,
                                    int kt, int lane, uint4* buf) {
    #pragma unroll
    for (int i = 0; i < 4; i++) {
        int mt = mt0 + i;
        buf[i] = (mt < m_tiles) ? __ldg(&Af[((size_t)mt * KT + kt) * 32 + lane])
                                : make_uint4(0u, 0u, 0u, 0u);
    }
}
__device__ __forceinline__ void ldB(const uint2* __restrict__ Bf, int nt0, int n_tiles,
                                    int kt, int lane, uint2* buf) {
    #pragma unroll
    for (int j = 0; j < 4; j++) {
        int nt = nt0 + j;
        buf[j] = (nt < n_tiles) ? __ldg(&Bf[((size_t)nt * KT + kt) * 32 + lane])
                                : make_uint2(0u, 0u);
    }
}

// ---------------- bf16 tensor-core GEMM on fragment-order operands ----------------
// CTA: 128 rows x 128 cols, 8 warps (2 m x 4 n), warp = 64x32 (4 m-tiles x 4 n-tiles)
__global__ __launch_bounds__(256, 1)
void gemm_bf16(const uint4* __restrict__ Af, const uint2* __restrict__ Bf,
               const float* __restrict__ bias, float* __restrict__ C,
               int M, int Nc, int m_tiles, int n_tiles) {
    int lane = threadIdx.x & 31;
    int wid  = threadIdx.x >> 5;
    int wm = wid >> 2, wn = wid & 3;
    int mt0 = blockIdx.y * 8 + wm * 4;
    int nt0 = blockIdx.x * 16 + wn * 4;

    float acc[4][4][4] = {};
    uint4 aP[4], aQ[4];
    uint2 bP[4], bQ[4];

    ldA(Af, mt0, m_tiles, 0, lane, aP);
    ldB(Bf, nt0, n_tiles, 0, lane, bP);

    for (int kt = 0; kt < KT; kt += 2) {
        ldA(Af, mt0, m_tiles, kt + 1, lane, aQ);
        ldB(Bf, nt0, n_tiles, kt + 1, lane, bQ);
        #pragma unroll
        for (int i = 0; i < 4; i++)
            #pragma unroll
            for (int j = 0; j < 4; j++)
                mma16816(acc[i][j], aP[i], bP[j]);
        if (kt + 2 < KT) {
            ldA(Af, mt0, m_tiles, kt + 2, lane, aP);
            ldB(Bf, nt0, n_tiles, kt + 2, lane, bP);
        }
        #pragma unroll
        for (int i = 0; i < 4; i++)
            #pragma unroll
            for (int j = 0; j < 4; j++)
                mma16816(acc[i][j], aQ[i], bQ[j]);
    }

    int g = lane >> 2, t2 = (lane & 3) * 2;
    #pragma unroll
    for (int i = 0; i < 4; i++) {
        int mt = mt0 + i;
        if (mt >= m_tiles) continue;
        int r0 = mt * 16 + g;
        #pragma unroll
        for (int j = 0; j < 4; j++) {
            int nt = nt0 + j;
            if (nt >= n_tiles) continue;
            int c0 = nt * 8 + t2;
            float bx = 0.f, by = 0.f;
            if (bias) { bx = bias[c0]; by = bias[c0 + 1]; }
            if (r0 < M) {
                float2 v = make_float2(acc[i][j][0] + bx, acc[i][j][1] + by);
                *(float2*)&C[(size_t)r0 * Nc + c0] = v;
            }
            int r1 = r0 + 8;
            if (r1 < M) {
                float2 v = make_float2(acc[i][j][2] + bx, acc[i][j][3] + by);
                *(float2*)&C[(size_t)r1 * Nc + c0] = v;
            }
        }
    }
}

// ---------------- W_att [8,256,32] -> W_cat [256, 256] ----------------
__global__ void make_wcat(const float* __restrict__ W_att, float* __restrict__ Wcat) {
    int idx = blockIdx.x * blockDim.x + threadIdx.x;
    if (idx >= F * F) return;
    int f = idx >> 8;
    int c = idx & 255;
    int i = c >> 5, j = c & 31;
    Wcat[idx] = W_att[((size_t)i * F + f) * FH + j];
}

// ---------------- zero/bias init of accumulators ----------------
__global__ void init_buffers(float* __restrict__ hp, float* __restrict__ rowsum,
                             float* __restrict__ h2, const float* __restrict__ b_gc,
                             float* __restrict__ rowsumo, float* __restrict__ hpo, int N) {
    int idx = blockIdx.x * blockDim.x + threadIdx.x;
    int total = N * F;
    if (idx >= total) return;
    hp[idx] = 0.f;
    h2[idx] = b_gc[idx & 255];
    if (idx < N * NH) rowsum[idx] = 0.f;
    if (idx < N)      rowsumo[idx] = 0.f;
    if (idx < N * NC) hpo[idx] = 0.f;
}

// ---------------- per-node attention scores s1,s2 [N,8] ----------------
__global__ void attn_scores(const float* __restrict__ H, const float* __restrict__ a1,
                            const float* __restrict__ a2, float* __restrict__ s1,
                            float* __restrict__ s2, int N) {
    int n = blockIdx.x;
    if (n >= N) return;
    int w = threadIdx.x >> 5;
    int lane = threadIdx.x & 31;
    float h = H[(size_t)n * F + w * FH + lane];
    float v1 = h * a1[w * FH + lane];
    float v2 = h * a2[w * FH + lane];
    #pragma unroll
    for (int o = 16; o > 0; o >>= 1) {
        v1 += __shfl_xor_sync(0xffffffffu, v1, o);
        v2 += __shfl_xor_sync(0xffffffffu, v2, o);
    }
    if (lane == 0) { s1[n * NH + w] = v1; s2[n * NH + w] = v2; }
}

// ---------------- fused edge pass: att coeff + rowsum + hp scatter ----------------
__global__ void edge_fused(const int* __restrict__ row, const int* __restrict__ col,
                           const float* __restrict__ s1, const float* __restrict__ s2,
                           const float* __restrict__ H, float* __restrict__ hp,
                           float* __restrict__ rowsum, int E) {
    int e = blockIdx.x * 4 + (threadIdx.x >> 6);
    if (e >= E) return;
    int u = threadIdx.x & 63;
    int head = u >> 3;
    int r = __ldg(row + e), c = __ldg(col + e);
    float lg = __ldg(s1 + r * NH + head) + __ldg(s2 + c * NH + head);
    float l = lg > 0.f ? lg : 0.2f * lg;
    float a = __expf(-l);
    if ((u & 7) == 0) atomicAdd(&rowsum[r * NH + head], a);
    float4 h4 = *(const float4*)(H + (size_t)c * F + 4 * u);
    red_add_v4(hp + (size_t)r * F + 4 * u,
               make_float4(a * h4.x, a * h4.y, a * h4.z, a * h4.w));
}

// ---------------- normalize + elu -> h1 (in place over hp) ----------------
__global__ void norm_elu(float* __restrict__ hp, const float* __restrict__ rowsum, int N) {
    int idx = blockIdx.x * blockDim.x + threadIdx.x;
    if (idx >= N * F) return;
    int n = idx >> 8;
    int i = (idx & 255) >> 5;
    float v = hp[idx] / (rowsum[n * NH + i] + 1e-16f);
    hp[idx] = v > 0.f ? v : (expf(v) - 1.f);
}

// ---------------- GraphConv scatter: h2[row] += support[col] ----------------
__global__ void gc_aggregate(const int* __restrict__ row, const int* __restrict__ col,
                             const float* __restrict__ sup, float* __restrict__ h2, int E) {
    int e = blockIdx.x * 4 + (threadIdx.x >> 6);
    if (e >= E) return;
    int u = threadIdx.x & 63;
    int r = __ldg(row + e), c = __ldg(col + e);
    float4 s4 = *(const float4*)(sup + (size_t)c * F + 4 * u);
    red_add_v4(h2 + (size_t)r * F + 4 * u, s4);
}

// ---------------- output-head scores (dim 40): one warp per node ----------------
__global__ void out_scores(const float* __restrict__ ho, const float* __restrict__ a1o,
                           const float* __restrict__ a2o, float* __restrict__ s1o,
                           float* __restrict__ s2o, int N) {
    int n = blockIdx.x * 8 + (threadIdx.x >> 5);
    if (n >= N) return;
    int lane = threadIdx.x & 31;
    float h0 = ho[(size_t)n * NC + lane];
    float v1 = h0 * a1o[lane];
    float v2 = h0 * a2o[lane];
    if (lane < NC - 32) {
        float h1v = ho[(size_t)n * NC + 32 + lane];
        v1 += h1v * a1o[32 + lane];
        v2 += h1v * a2o[32 + lane];
    }
    #pragma unroll
    for (int o = 16; o > 0; o >>= 1) {
        v1 += __shfl_xor_sync(0xffffffffu, v1, o);
        v2 += __shfl_xor_sync(0xffffffffu, v2, o);
    }
    if (lane == 0) { s1o[n] = v1; s2o[n] = v2; }
}

// ---------------- fused output edge pass ----------------
__global__ void out_fused(const int* __restrict__ row, const int* __restrict__ col,
                          const float* __restrict__ s1o, const float* __restrict__ s2o,
                          const float* __restrict__ ho, float* __restrict__ hpo,
                          float* __restrict__ rowsumo, int E) {
    int e = blockIdx.x * 16 + (threadIdx.x >> 4);
    if (e >= E) return;
    int q = threadIdx.x & 15;
    int r = __ldg(row + e), c = __ldg(col + e);
    float lg = __ldg(s1o + r) + __ldg(s2o + c);
    float l = lg > 0.f ? lg : 0.2f * lg;
    float a = __expf(-l);
    if (q == 0) atomicAdd(&rowsumo[r], a);
    if (q < 10) {
        float4 h4 = *(const float4*)(ho + (size_t)c * NC + 4 * q);
        red_add_v4(hpo + (size_t)r * NC + 4 * q,
                   make_float4(a * h4.x, a * h4.y, a * h4.z, a * h4.w));
    }
}

// ---------------- normalize + elu + log_softmax over 40 classes ----------------
__global__ void final_xo(const float* __restrict__ hpo, const float* __restrict__ rowsumo,
                         float* __restrict__ out, int N) {
    int n = blockIdx.x * 8 + (threadIdx.x >> 5);
    if (n >= N) return;
    int lane = threadIdx.x & 31;
    float rs = rowsumo[n] + 1e-16f;
    float x0 = hpo[(size_t)n * NC + lane] / rs;
    x0 = x0 > 0.f ? x0 : (expf(x0) - 1.f);
    float x1 = -1e30f;
    if (lane < NC - 32) {
        x1 = hpo[(size_t)n * NC + 32 + lane] / rs;
        x1 = x1 > 0.f ? x1 : (expf(x1) - 1.f);
    }
    float m = fmaxf(x0, x1);
    #pragma unroll
    for (int o = 16; o > 0; o >>= 1) m = fmaxf(m, __shfl_xor_sync(0xffffffffu, m, o));
    float s = expf(x0 - m) + (lane < NC - 32 ? expf(x1 - m) : 0.f);
    #pragma unroll
    for (int o = 16; o > 0; o >>= 1) s += __shfl_xor_sync(0xffffffffu, s, o);
    float lse = logf(s) + m;
    out[(size_t)n * NC + lane] = x0 - lse;
    if (lane < NC - 32) out[(size_t)n * NC + 32 + lane] = x1 - lse;
}

// =============================================================================
extern "C" void kernel_launch(void* const* d_in, const int* in_sizes, int n_in,
                              void* d_out, int out_size) {
    const float* x     = (const float*)d_in[0];
    const int*   eidx  = (const int*)d_in[1];
    const float* W_att = (const float*)d_in[2];
    const float* a1    = (const float*)d_in[3];
    const float* a2    = (const float*)d_in[4];
    const float* W_out = (const float*)d_in[5];
    const float* a1o   = (const float*)d_in[6];
    const float* a2o   = (const float*)d_in[7];
    const float* W_gc  = (const float*)d_in[8];
    const float* b_gc  = (const float*)d_in[9];
    const float* W_enc = (const float*)d_in[10];
    const float* b_enc = (const float*)d_in[11];
    float* out = (float*)d_out;

    int N = in_sizes[0] / F;
    int E = in_sizes[1] / 2;
    const int* row = eidx;
    const int* col = eidx + E;
    int m_tiles = (N + 15) / 16;

    float *Wcat, *H, *s1, *s2, *rowsum, *hp, *support, *h2;
    float *ho, *s1o, *s2o, *rowsumo, *hpo;
    uint4 *A2a, *A2b;
    uint2 *B2att, *B2gc, *B2out, *B2enc;
    cudaGetSymbolAddress((void**)&Wcat,    g_Wcat);
    cudaGetSymbolAddress((void**)&H,       g_H);
    cudaGetSymbolAddress((void**)&s1,      g_s1);
    cudaGetSymbolAddress((void**)&s2,      g_s2);
    cudaGetSymbolAddress((void**)&rowsum,  g_rowsum);
    cudaGetSymbolAddress((void**)&hp,      g_hp);
    cudaGetSymbolAddress((void**)&support, g_support);
    cudaGetSymbolAddress((void**)&h2,      g_h2);
    cudaGetSymbolAddress((void**)&ho,      g_ho);
    cudaGetSymbolAddress((void**)&s1o,     g_s1o);
    cudaGetSymbolAddress((void**)&s2o,     g_s2o);
    cudaGetSymbolAddress((void**)&rowsumo, g_rowsumo);
    cudaGetSymbolAddress((void**)&hpo,     g_hpo);
    cudaGetSymbolAddress((void**)&A2a,     g_A2a);
    cudaGetSymbolAddress((void**)&A2b,     g_A2b);
    cudaGetSymbolAddress((void**)&B2att,   g_B2att);
    cudaGetSymbolAddress((void**)&B2gc,    g_B2gc);
    cudaGetSymbolAddress((void**)&B2out,   g_B2out);
    cudaGetSymbolAddress((void**)&B2enc,   g_B2enc);

    long long aWords = (long long)m_tiles * KT * 32 * 4;
    int aBlocks = (int)((aWords + 255) / 256);

    // 0) repack W_att, init accumulators, split weights to bf16x3 fragments
    make_wcat<<<(F * F + 255) / 256, 256>>>(W_att, Wcat);
    init_buffers<<<(N * F + 255) / 256, 256>>>(hp, rowsum, h2, b_gc, rowsumo, hpo, N);
    split_b<<<(32 * KT * 32 * 2 + 255) / 256, 256>>>(Wcat,  (unsigned*)B2att, 32, 256);
    split_b<<<(32 * KT * 32 * 2 + 255) / 256, 256>>>(W_gc,  (unsigned*)B2gc,  32, 256);
    split_b<<<( 5 * KT * 32 * 2 + 255) / 256, 256>>>(W_out, (unsigned*)B2out,  5,  40);
    split_b<<<(16 * KT * 32 * 2 + 255) / 256, 256>>>(W_enc, (unsigned*)B2enc, 16, 128);

    // 1) H = x @ Wcat  (split x, tensor GEMM)
    split_a<<<aBlocks, 256>>>(x, (unsigned*)A2a, m_tiles, N);
    {
        dim3 grid(2, (m_tiles + 7) / 8);
        gemm_bf16<<<grid, 256>>>(A2a, B2att, nullptr, H, N, 256, m_tiles, 32);
    }

    // 2) per-node attention scores
    attn_scores<<<N, 256>>>(H, a1, a2, s1, s2, N);

    // 3+4) fused edge pass: att coeff, rowsum, hp[row] += att*H[col]
    edge_fused<<<(E + 3) / 4, 256>>>(row, col, s1, s2, H, hp, rowsum, E);

    // 5) h1 = elu(hp / rowsum)  (in place)
    norm_elu<<<(N * F + 255) / 256, 256>>>(hp, rowsum, N);

    // 6) support = h1 @ W_gc
    split_a<<<aBlocks, 256>>>(hp, (unsigned*)A2b, m_tiles, N);
    {
        dim3 grid(2, (m_tiles + 7) / 8);
        gemm_bf16<<<grid, 256>>>(A2b, B2gc, nullptr, support, N, 256, m_tiles, 32);
    }

    // 7) h2 = b_gc + sum support[col] over edges
    gc_aggregate<<<(E + 3) / 4, 256>>>(row, col, support, h2, E);

    // 8) ho = h2 @ W_out  [N,40]
    split_a<<<aBlocks, 256>>>(h2, (unsigned*)A2a, m_tiles, N);
    {
        dim3 grid(1, (m_tiles + 7) / 8);
        gemm_bf16<<<grid, 256>>>(A2a, B2out, nullptr, ho, N, NC, m_tiles, 5);
    }

    // 9) output-head attention (scores + fused edge pass)
    out_scores<<<(N + 7) / 8, 256>>>(ho, a1o, a2o, s1o, s2o, N);
    out_fused<<<(E + 15) / 16, 256>>>(row, col, s1o, s2o, ho, hpo, rowsumo, E);

    // 10) xo = log_softmax(elu(hpo / rowsumo)) -> out[0 : N*40]
    final_xo<<<(N + 7) / 8, 256>>>(hpo, rowsumo, out, N);

    // 11) y = h1 @ W_enc + b_enc ; z = h2 @ W_enc + b_enc
    {
        dim3 grid(1, (m_tiles + 7) / 8);
        gemm_bf16<<<grid, 256>>>(A2b, B2enc, b_enc, out + (size_t)N * NC, N, NS, m_tiles, 16);
        gemm_bf16<<<grid, 256>>>(A2a, B2enc, b_enc, out + (size_t)N * (NC + NS), N, NS, m_tiles, 16);
    }
}

// round 9
// speedup vs baseline: 1.1736x; 1.0785x over previous
#include <cuda_runtime.h>
#include <cuda_bf16.h>
#include <math.h>

// Problem constants (shapes fixed by the dataset)
#define NMAX 50000
#define EMAX 800000
#define F    256   // nfeat == nhid*nheads == hid
#define NH   8     // heads
#define FH   32    // per-head dim
#define NC   40    // nclass
#define NS   128   // nstruc
// bf16x3 split: K2 = 3*256 = 768 -> A = [Ahi|Alo|Ahi], B = [Bhi|Bhi|Blo]
#define KT   48    // k16 tiles in K2
#define MT_MAX 3125  // NMAX/16

// ---------------- scratch (device globals: allocation-free) ----------------
__device__ float g_Wcat[F * F];                   // repacked W_att
__device__ float g_H[(size_t)NMAX * F];           // per-head features (concat)
__device__ float g_s1[NMAX * NH];
__device__ float g_s2[NMAX * NH];
__device__ float g_hp[(size_t)NMAX * F];          // h1
__device__ float g_support[(size_t)NMAX * F];
__device__ float g_h2[(size_t)NMAX * F];
__device__ float g_ho[NMAX * NC];
__device__ float g_s1o[NMAX];
__device__ float g_s2o[NMAX];

// CSR scratch
__device__ int g_deg[NMAX];
__device__ int g_off[NMAX + 1];
__device__ int g_cur[NMAX];
__device__ int g_ecol[EMAX];

// bf16 split operands in mma-fragment order
__device__ uint4 g_A2a[(size_t)MT_MAX * KT * 32];
__device__ uint4 g_A2b[(size_t)MT_MAX * KT * 32];
__device__ uint2 g_B2att[32 * KT * 32];
__device__ uint2 g_B2gc [32 * KT * 32];
__device__ uint2 g_B2out[ 5 * KT * 32];
__device__ uint2 g_B2enc[16 * KT * 32];

// bf16 mma: D += A(16x16) * B(16x8), row.col, fp32 accum
__device__ __forceinline__ void mma16816(float* d, const uint4& a, const uint2& b) {
    asm volatile(
        "mma.sync.aligned.m16n8k16.row.col.f32.bf16.bf16.f32 "
        "{%0,%1,%2,%3}, {%4,%5,%6,%7}, {%8,%9}, {%0,%1,%2,%3};"
        : "+f"(d[0]), "+f"(d[1]), "+f"(d[2]), "+f"(d[3])
        : "r"(a.x), "r"(a.y), "r"(a.z), "r"(a.w), "r"(b.x), "r"(b.y));
}

__device__ __forceinline__ unsigned short bf_hi(float a) {
    return __bfloat16_as_ushort(__float2bfloat16(a));
}
__device__ __forceinline__ unsigned short bf_lo(float a) {
    float h = __bfloat162float(__float2bfloat16(a));
    return __bfloat16_as_ushort(__float2bfloat16(a - h));
}

// A split mapping over tripled k2: [0,F) hi, [F,2F) lo, [2F,3F) hi
__device__ __forceinline__ unsigned short split_elem_a(const float* base, int k2) {
    if (k2 < F)        return bf_hi(base[k2]);
    else if (k2 < 2*F) return bf_lo(base[k2 - F]);
    else               return bf_hi(base[k2 - 2*F]);
}

// ---------------- A [M,256] fp32 -> fragment-order bf16x3 ----------------
__global__ void split_a(const float* __restrict__ A, unsigned* __restrict__ out,
                        int m_tiles, int M) {
    long long idx = (long long)blockIdx.x * blockDim.x + threadIdx.x;
    long long total = (long long)m_tiles * KT * 32 * 4;
    if (idx >= total) return;
    int r    = (int)(idx & 3);
    int lane = (int)((idx >> 2) & 31);
    long long rest = idx >> 7;
    int kt   = (int)(rest % KT);
    int mt   = (int)(rest / KT);
    int g = lane >> 2, t2 = (lane & 3) * 2;
    int row   = mt * 16 + g + (r & 1) * 8;
    int kbase = kt * 16 + t2 + (r >> 1) * 8;
    unsigned w = 0;
    if (row < M) {
        const float* base = A + (size_t)row * F;
        unsigned short e0 = split_elem_a(base, kbase);
        unsigned short e1 = split_elem_a(base, kbase + 1);
        w = (unsigned)e0 | ((unsigned)e1 << 16);
    }
    out[idx] = w;
}

// ---------------- B [256,Nc] fp32 -> fragment-order bf16x3 ----------------
// B mapping over tripled k2: [0,F) hi, [F,2F) hi, [2F,3F) lo
__global__ void split_b(const float* __restrict__ B, unsigned* __restrict__ out,
                        int n_tiles, int Nc) {
    int idx = blockIdx.x * blockDim.x + threadIdx.x;
    int total = n_tiles * KT * 32 * 2;
    if (idx >= total) return;
    int r    = idx & 1;
    int lane = (idx >> 1) & 31;
    int rest = idx >> 6;
    int kt   = rest % KT;
    int nt   = rest / KT;
    int g = lane >> 2, t2 = (lane & 3) * 2;
    int n = nt * 8 + g;
    int kbase = kt * 16 + t2 + r * 8;
    unsigned w = 0;
    #pragma unroll
    for (int p = 0; p < 2; p++) {
        int k2 = kbase + p;
        unsigned short bits;
        if (k2 < 2*F) {
            int k = (k2 < F) ? k2 : (k2 - F);
            bits = bf_hi(B[(size_t)k * Nc + n]);
        } else {
            bits = bf_lo(B[(size_t)(k2 - 2*F) * Nc + n]);
        }
        w |= (unsigned)bits << (16 * p);
    }
    out[idx] = w;
}

// ---------------- fragment loads ----------------
__device__ __forceinline__ void ldA(const uint4* __restrict__ Af, int mt0, int m_tiles,
                                    int kt, int lane, uint4* buf) {
    #pragma unroll
    for (int i = 0; i < 4; i++) {
        int mt = mt0 + i;
        buf[i] = (mt < m_tiles) ? __ldg(&Af[((size_t)mt * KT + kt) * 32 + lane])
                                : make_uint4(0u, 0u, 0u, 0u);
    }
}
__device__ __forceinline__ void ldB(const uint2* __restrict__ Bf, int nt0, int n_tiles,
                                    int kt, int lane, uint2* buf) {
    #pragma unroll
    for (int j = 0; j < 4; j++) {
        int nt = nt0 + j;
        buf[j] = (nt < n_tiles) ? __ldg(&Bf[((size_t)nt * KT + kt) * 32 + lane])
                                : make_uint2(0u, 0u);
    }
}

// ---------------- bf16 tensor-core GEMM on fragment-order operands ----------------
__global__ __launch_bounds__(256, 1)
void gemm_bf16(const uint4* __restrict__ Af, const uint2* __restrict__ Bf,
               const float* __restrict__ bias, float* __restrict__ C,
               int M, int Nc, int m_tiles, int n_tiles) {
    int lane = threadIdx.x & 31;
    int wid  = threadIdx.x >> 5;
    int wm = wid >> 2, wn = wid & 3;
    int mt0 = blockIdx.y * 8 + wm * 4;
    int nt0 = blockIdx.x * 16 + wn * 4;

    float acc[4][4][4] = {};
    uint4 aP[4], aQ[4];
    uint2 bP[4], bQ[4];

    ldA(Af, mt0, m_tiles, 0, lane, aP);
    ldB(Bf, nt0, n_tiles, 0, lane, bP);

    for (int kt = 0; kt < KT; kt += 2) {
        ldA(Af, mt0, m_tiles, kt + 1, lane, aQ);
        ldB(Bf, nt0, n_tiles, kt + 1, lane, bQ);
        #pragma unroll
        for (int i = 0; i < 4; i++)
            #pragma unroll
            for (int j = 0; j < 4; j++)
                mma16816(acc[i][j], aP[i], bP[j]);
        if (kt + 2 < KT) {
            ldA(Af, mt0, m_tiles, kt + 2, lane, aP);
            ldB(Bf, nt0, n_tiles, kt + 2, lane, bP);
        }
        #pragma unroll
        for (int i = 0; i < 4; i++)
            #pragma unroll
            for (int j = 0; j < 4; j++)
                mma16816(acc[i][j], aQ[i], bQ[j]);
    }

    int g = lane >> 2, t2 = (lane & 3) * 2;
    #pragma unroll
    for (int i = 0; i < 4; i++) {
        int mt = mt0 + i;
        if (mt >= m_tiles) continue;
        int r0 = mt * 16 + g;
        #pragma unroll
        for (int j = 0; j < 4; j++) {
            int nt = nt0 + j;
            if (nt >= n_tiles) continue;
            int c0 = nt * 8 + t2;
            float bx = 0.f, by = 0.f;
            if (bias) { bx = bias[c0]; by = bias[c0 + 1]; }
            if (r0 < M) {
                float2 v = make_float2(acc[i][j][0] + bx, acc[i][j][1] + by);
                *(float2*)&C[(size_t)r0 * Nc + c0] = v;
            }
            int r1 = r0 + 8;
            if (r1 < M) {
                float2 v = make_float2(acc[i][j][2] + bx, acc[i][j][3] + by);
                *(float2*)&C[(size_t)r1 * Nc + c0] = v;
            }
        }
    }
}

// ---------------- W_att [8,256,32] -> W_cat [256, 256] ----------------
__global__ void make_wcat(const float* __restrict__ W_att, float* __restrict__ Wcat) {
    int idx = blockIdx.x * blockDim.x + threadIdx.x;
    if (idx >= F * F) return;
    int f = idx >> 8;
    int c = idx & 255;
    int i = c >> 5, j = c & 31;
    Wcat[idx] = W_att[((size_t)i * F + f) * FH + j];
}

// ---------------- CSR build ----------------
__global__ void zero_deg(int* __restrict__ deg, int N) {
    int i = blockIdx.x * blockDim.x + threadIdx.x;
    if (i < N) deg[i] = 0;
}
__global__ void count_deg(const int* __restrict__ row, int* __restrict__ deg, int E) {
    int e = blockIdx.x * blockDim.x + threadIdx.x;
    if (e < E) atomicAdd(&deg[row[e]], 1);
}
// single-CTA exclusive scan -> off[0..N], also primes cur
__global__ void scan_offsets(const int* __restrict__ deg, int* __restrict__ off,
                             int* __restrict__ cur, int N) {
    __shared__ int sums[1024];
    int tid = threadIdx.x;
    int chunk = (N + 1023) / 1024;
    int start = tid * chunk;
    int end = min(start + chunk, N);
    int s = 0;
    for (int i = start; i < end; i++) s += deg[i];
    sums[tid] = s;
    __syncthreads();
    for (int d = 1; d < 1024; d <<= 1) {
        int v = (tid >= d) ? sums[tid - d] : 0;
        __syncthreads();
        sums[tid] += v;
        __syncthreads();
    }
    int run = (tid == 0) ? 0 : sums[tid - 1];
    for (int i = start; i < end; i++) {
        off[i] = run;
        cur[i] = run;
        run += deg[i];
    }
    if (tid == 0) off[N] = sums[1023];
}
__global__ void build_csr(const int* __restrict__ row, const int* __restrict__ col,
                          int* __restrict__ cur, int* __restrict__ ecol, int E) {
    int e = blockIdx.x * blockDim.x + threadIdx.x;
    if (e >= E) return;
    int pos = atomicAdd(&cur[row[e]], 1);
    ecol[pos] = col[e];
}

// ---------------- per-node attention scores s1,s2 [N,8] ----------------
__global__ void attn_scores(const float* __restrict__ H, const float* __restrict__ a1,
                            const float* __restrict__ a2, float* __restrict__ s1,
                            float* __restrict__ s2, int N) {
    int n = blockIdx.x;
    if (n >= N) return;
    int w = threadIdx.x >> 5;
    int lane = threadIdx.x & 31;
    float h = H[(size_t)n * F + w * FH + lane];
    float v1 = h * a1[w * FH + lane];
    float v2 = h * a2[w * FH + lane];
    #pragma unroll
    for (int o = 16; o > 0; o >>= 1) {
        v1 += __shfl_xor_sync(0xffffffffu, v1, o);
        v2 += __shfl_xor_sync(0xffffffffu, v2, o);
    }
    if (lane == 0) { s1[n * NH + w] = v1; s2[n * NH + w] = v2; }
}

// ---------------- GAT layer 1: CSR gather, fused att+rowsum+norm+elu ----------------
// one CTA(256) per node; warp = head; thread owns feature tid
__global__ void gat_gather(const int* __restrict__ off, const int* __restrict__ ecol,
                           const float* __restrict__ s1, const float* __restrict__ s2,
                           const float* __restrict__ H, float* __restrict__ hp, int N) {
    int n = blockIdx.x;
    if (n >= N) return;
    int tid = threadIdx.x;
    int head = tid >> 5;
    int start = off[n], end = off[n + 1];
    float s1v = __ldg(s1 + n * NH + head);
    float acc = 0.f, rsum = 0.f;
    int p = start;
    for (; p + 1 < end; p += 2) {
        int c0 = __ldg(ecol + p);
        int c1 = __ldg(ecol + p + 1);
        float lg0 = s1v + __ldg(s2 + c0 * NH + head);
        float lg1 = s1v + __ldg(s2 + c1 * NH + head);
        float h0 = __ldg(H + (size_t)c0 * F + tid);
        float h1 = __ldg(H + (size_t)c1 * F + tid);
        float l0 = lg0 > 0.f ? lg0 : 0.2f * lg0;
        float l1 = lg1 > 0.f ? lg1 : 0.2f * lg1;
        float a0 = __expf(-l0);
        float a1v = __expf(-l1);
        rsum += a0 + a1v;
        acc += a0 * h0 + a1v * h1;
    }
    if (p < end) {
        int c = __ldg(ecol + p);
        float lg = s1v + __ldg(s2 + c * NH + head);
        float l = lg > 0.f ? lg : 0.2f * lg;
        float a = __expf(-l);
        rsum += a;
        acc += a * __ldg(H + (size_t)c * F + tid);
    }
    float v = acc / (rsum + 1e-16f);
    hp[(size_t)n * F + tid] = v > 0.f ? v : (expf(v) - 1.f);
}

// ---------------- GraphConv: CSR gather + bias ----------------
__global__ void gc_gather(const int* __restrict__ off, const int* __restrict__ ecol,
                          const float* __restrict__ sup, const float* __restrict__ b_gc,
                          float* __restrict__ h2, int N) {
    int n = blockIdx.x;
    if (n >= N) return;
    int tid = threadIdx.x;
    int start = off[n], end = off[n + 1];
    float acc = __ldg(b_gc + tid);
    int p = start;
    for (; p + 1 < end; p += 2) {
        int c0 = __ldg(ecol + p);
        int c1 = __ldg(ecol + p + 1);
        acc += __ldg(sup + (size_t)c0 * F + tid) + __ldg(sup + (size_t)c1 * F + tid);
    }
    if (p < end) {
        int c = __ldg(ecol + p);
        acc += __ldg(sup + (size_t)c * F + tid);
    }
    h2[(size_t)n * F + tid] = acc;
}

// ---------------- output-head scores (dim 40): one warp per node ----------------
__global__ void out_scores(const float* __restrict__ ho, const float* __restrict__ a1o,
                           const float* __restrict__ a2o, float* __restrict__ s1o,
                           float* __restrict__ s2o, int N) {
    int n = blockIdx.x * 8 + (threadIdx.x >> 5);
    if (n >= N) return;
    int lane = threadIdx.x & 31;
    float h0 = ho[(size_t)n * NC + lane];
    float v1 = h0 * a1o[lane];
    float v2 = h0 * a2o[lane];
    if (lane < NC - 32) {
        float h1v = ho[(size_t)n * NC + 32 + lane];
        v1 += h1v * a1o[32 + lane];
        v2 += h1v * a2o[32 + lane];
    }
    #pragma unroll
    for (int o = 16; o > 0; o >>= 1) {
        v1 += __shfl_xor_sync(0xffffffffu, v1, o);
        v2 += __shfl_xor_sync(0xffffffffu, v2, o);
    }
    if (lane == 0) { s1o[n] = v1; s2o[n] = v2; }
}

// ---------------- output head: CSR gather + elu + log_softmax fused ----------------
// one warp per node; lane owns dims lane and lane+32 (<40)
__global__ void out_gather(const int* __restrict__ off, const int* __restrict__ ecol,
                           const float* __restrict__ s1o, const float* __restrict__ s2o,
                           const float* __restrict__ ho, float* __restrict__ out, int N) {
    int n = blockIdx.x * 8 + (threadIdx.x >> 5);
    if (n >= N) return;
    int lane = threadIdx.x & 31;
    int start = off[n], end = off[n + 1];
    float s1v = __ldg(s1o + n);
    float acc0 = 0.f, acc1 = 0.f, rsum = 0.f;
    for (int p = start; p < end; p++) {
        int c = __ldg(ecol + p);
        float lg = s1v + __ldg(s2o + c);
        float l = lg > 0.f ? lg : 0.2f * lg;
        float a = __expf(-l);
        rsum += a;
        acc0 += a * __ldg(ho + (size_t)c * NC + lane);
        if (lane < NC - 32)
            acc1 += a * __ldg(ho + (size_t)c * NC + 32 + lane);
    }
    float rs = rsum + 1e-16f;
    float x0 = acc0 / rs;
    x0 = x0 > 0.f ? x0 : (expf(x0) - 1.f);
    float x1 = -1e30f;
    if (lane < NC - 32) {
        x1 = acc1 / rs;
        x1 = x1 > 0.f ? x1 : (expf(x1) - 1.f);
    }
    float m = fmaxf(x0, x1);
    #pragma unroll
    for (int o = 16; o > 0; o >>= 1) m = fmaxf(m, __shfl_xor_sync(0xffffffffu, m, o));
    float s = expf(x0 - m) + (lane < NC - 32 ? expf(x1 - m) : 0.f);
    #pragma unroll
    for (int o = 16; o > 0; o >>= 1) s += __shfl_xor_sync(0xffffffffu, s, o);
    float lse = logf(s) + m;
    out[(size_t)n * NC + lane] = x0 - lse;
    if (lane < NC - 32) out[(size_t)n * NC + 32 + lane] = x1 - lse;
}

// =============================================================================
extern "C" void kernel_launch(void* const* d_in, const int* in_sizes, int n_in,
                              void* d_out, int out_size) {
    const float* x     = (const float*)d_in[0];
    const int*   eidx  = (const int*)d_in[1];
    const float* W_att = (const float*)d_in[2];
    const float* a1    = (const float*)d_in[3];
    const float* a2    = (const float*)d_in[4];
    const float* W_out = (const float*)d_in[5];
    const float* a1o   = (const float*)d_in[6];
    const float* a2o   = (const float*)d_in[7];
    const float* W_gc  = (const float*)d_in[8];
    const float* b_gc  = (const float*)d_in[9];
    const float* W_enc = (const float*)d_in[10];
    const float* b_enc = (const float*)d_in[11];
    float* out = (float*)d_out;

    int N = in_sizes[0] / F;
    int E = in_sizes[1] / 2;
    const int* row = eidx;
    const int* col = eidx + E;
    int m_tiles = (N + 15) / 16;

    float *Wcat, *H, *s1, *s2, *hp, *support, *h2, *ho, *s1o, *s2o;
    int *deg, *off, *cur, *ecol;
    uint4 *A2a, *A2b;
    uint2 *B2att, *B2gc, *B2out, *B2enc;
    cudaGetSymbolAddress((void**)&Wcat,    g_Wcat);
    cudaGetSymbolAddress((void**)&H,       g_H);
    cudaGetSymbolAddress((void**)&s1,      g_s1);
    cudaGetSymbolAddress((void**)&s2,      g_s2);
    cudaGetSymbolAddress((void**)&hp,      g_hp);
    cudaGetSymbolAddress((void**)&support, g_support);
    cudaGetSymbolAddress((void**)&h2,      g_h2);
    cudaGetSymbolAddress((void**)&ho,      g_ho);
    cudaGetSymbolAddress((void**)&s1o,     g_s1o);
    cudaGetSymbolAddress((void**)&s2o,     g_s2o);
    cudaGetSymbolAddress((void**)&deg,     g_deg);
    cudaGetSymbolAddress((void**)&off,     g_off);
    cudaGetSymbolAddress((void**)&cur,     g_cur);
    cudaGetSymbolAddress((void**)&ecol,    g_ecol);
    cudaGetSymbolAddress((void**)&A2a,     g_A2a);
    cudaGetSymbolAddress((void**)&A2b,     g_A2b);
    cudaGetSymbolAddress((void**)&B2att,   g_B2att);
    cudaGetSymbolAddress((void**)&B2gc,    g_B2gc);
    cudaGetSymbolAddress((void**)&B2out,   g_B2out);
    cudaGetSymbolAddress((void**)&B2enc,   g_B2enc);

    long long aWords = (long long)m_tiles * KT * 32 * 4;
    int aBlocks = (int)((aWords + 255) / 256);

    // 0) CSR build + weight prep
    zero_deg<<<(N + 255) / 256, 256>>>(deg, N);
    count_deg<<<(E + 255) / 256, 256>>>(row, deg, E);
    scan_offsets<<<1, 1024>>>(deg, off, cur, N);
    build_csr<<<(E + 255) / 256, 256>>>(row, col, cur, ecol, E);
    make_wcat<<<(F * F + 255) / 256, 256>>>(W_att, Wcat);
    split_b<<<(32 * KT * 32 * 2 + 255) / 256, 256>>>(Wcat,  (unsigned*)B2att, 32, 256);
    split_b<<<(32 * KT * 32 * 2 + 255) / 256, 256>>>(W_gc,  (unsigned*)B2gc,  32, 256);
    split_b<<<( 5 * KT * 32 * 2 + 255) / 256, 256>>>(W_out, (unsigned*)B2out,  5,  40);
    split_b<<<(16 * KT * 32 * 2 + 255) / 256, 256>>>(W_enc, (unsigned*)B2enc, 16, 128);

    // 1) H = x @ Wcat
    split_a<<<aBlocks, 256>>>(x, (unsigned*)A2a, m_tiles, N);
    {
        dim3 grid(2, (m_tiles + 7) / 8);
        gemm_bf16<<<grid, 256>>>(A2a, B2att, nullptr, H, N, 256, m_tiles, 32);
    }

    // 2) per-node attention scores
    attn_scores<<<N, 256>>>(H, a1, a2, s1, s2, N);

    // 3) GAT gather (fused att + rowsum + normalize + elu) -> h1
    gat_gather<<<N, 256>>>(off, ecol, s1, s2, H, hp, N);

    // 4) support = h1 @ W_gc
    split_a<<<aBlocks, 256>>>(hp, (unsigned*)A2b, m_tiles, N);
    {
        dim3 grid(2, (m_tiles + 7) / 8);
        gemm_bf16<<<grid, 256>>>(A2b, B2gc, nullptr, support, N, 256, m_tiles, 32);
    }

    // 5) h2 = b_gc + gather support
    gc_gather<<<N, 256>>>(off, ecol, support, b_gc, h2, N);

    // 6) ho = h2 @ W_out  [N,40]
    split_a<<<aBlocks, 256>>>(h2, (unsigned*)A2a, m_tiles, N);
    {
        dim3 grid(1, (m_tiles + 7) / 8);
        gemm_bf16<<<grid, 256>>>(A2a, B2out, nullptr, ho, N, NC, m_tiles, 5);
    }

    // 7) output head: scores + fused gather/softmax -> out[0 : N*40]
    out_scores<<<(N + 7) / 8, 256>>>(ho, a1o, a2o, s1o, s2o, N);
    out_gather<<<(N + 7) / 8, 256>>>(off, ecol, s1o, s2o, ho, out, N);

    // 8) y = h1 @ W_enc + b_enc ; z = h2 @ W_enc + b_enc
    {
        dim3 grid(1, (m_tiles + 7) / 8);
        gemm_bf16<<<grid, 256>>>(A2b, B2enc, b_enc, out + (size_t)N * NC, N, NS, m_tiles, 16);
        gemm_bf16<<<grid, 256>>>(A2a, B2enc, b_enc, out + (size_t)N * (NC + NS), N, NS, m_tiles, 16);
    }
}